// round 6
// baseline (speedup 1.0000x reference)
#include <cuda_runtime.h>
#include <math.h>
#include <stdint.h>

// ---------------- constants ----------------
#define C_CURV 0.05f
#define SQC    0.22360679774997896f              // sqrt(0.05)
#define MAXNORM (0.996f / 0.22360679774997896f)  // (1-4e-3)/sqrt(c)
#define MINN   1e-15f

#define BS   32
#define CIN  64
#define COUT 128
#define HW   64
#define NPIX 4096      // 64*64
#define HPAD 66        // padded rows (0 and 65 are halo)
#define T    68        // smem tile row stride (floats)
#define OCOL 4         // input col ci -> smem col ci+4 ; left halo at col 3

#define NT   512       // threads per block (main kernel)
#define CPB  4         // couts per block
#define TILE (HPAD * T)   // 4488 floats

// scratch (allocation-free rule: __device__ globals)
__device__ float g_sc[BS * CIN];   // logmap0 scale per (b,cin)
__device__ float g_bh[COUT];       // expmap0(bias)

// ---------------- packed f32x2 helpers ----------------
typedef unsigned long long u64t;
#define FMA2(d, a, b, c) \
    asm("fma.rn.f32x2 %0, %1, %2, %3;" : "=l"(d) : "l"(a), "l"(b), "l"(c))
#define MUL2(d, a, b) \
    asm("mul.rn.f32x2 %0, %1, %2;" : "=l"(d) : "l"(a), "l"(b))
#define PACK2(d, lo, hi) \
    asm("mov.b64 %0, {%1, %2};" : "=l"(d) : "f"(lo), "f"(hi))
#define UNPACK2(lo, hi, s) \
    asm("mov.b64 {%0, %1}, %2;" : "=f"(lo), "=f"(hi) : "l"(s))

#define CP16(dst, src) \
    asm volatile("cp.async.ca.shared.global [%0], [%1], 16;" :: "r"(dst), "l"(src))
#define CP_COMMIT() asm volatile("cp.async.commit_group;")
#define CP_WAIT1()  asm volatile("cp.async.wait_group 1;")
#define CP_WAIT0()  asm volatile("cp.async.wait_group 0;")

// ---------------- kernel A: logmap0 scales ----------------
__global__ void scale_kernel(const float* __restrict__ x) {
    int bc = blockIdx.x;                       // 0..2047
    const float* xp = x + (size_t)bc * NPIX;
    float s = 0.f;
    for (int i = threadIdx.x; i < NPIX; i += 256) { float v = xp[i]; s += v * v; }
    __shared__ float red[8];
    #pragma unroll
    for (int o = 16; o; o >>= 1) s += __shfl_xor_sync(0xffffffffu, s, o);
    if ((threadIdx.x & 31) == 0) red[threadIdx.x >> 5] = s;
    __syncthreads();
    if (threadIdx.x == 0) {
        float tot = 0.f;
        #pragma unroll
        for (int w = 0; w < 8; w++) tot += red[w];
        float n = fmaxf(sqrtf(tot), MINN);
        float a = fminf(SQC * n, 1.f - 1e-7f);
        float art = 0.5f * (log1pf(a) - log1pf(-a));
        g_sc[bc] = art / (SQC * n);
    }
}

// ---------------- kernel B: hyperbolic bias ----------------
__global__ void bias_kernel(const float* __restrict__ bias) {
    __shared__ float red[4];
    int t = threadIdx.x;                       // 128 threads
    float v = bias[t];
    float s = v * v;
    #pragma unroll
    for (int o = 16; o; o >>= 1) s += __shfl_xor_sync(0xffffffffu, s, o);
    if ((t & 31) == 0) red[t >> 5] = s;
    __syncthreads();
    float tot = red[0] + red[1] + red[2] + red[3];
    float n = fmaxf(sqrtf(tot), MINN);
    g_bh[t] = tanhf(SQC * n) * v / (SQC * n);
}

// ---------------- main kernel ----------------
__global__ __launch_bounds__(NT, 1)
void hypconv_kernel(const float* __restrict__ x, const float* __restrict__ w,
                    float* __restrict__ out) {
    __shared__ float buf[2][TILE];             // double-buffered RAW padded tiles
    __shared__ float ws[CPB * CIN * 9];        // weights for this block's 4 couts
    __shared__ float sc_s[CIN];                // logmap scales for this batch
    __shared__ float red[8][16];

    int b   = blockIdx.y;                      // 0..31
    int cog = blockIdx.x;                      // 0..31 (cout group)
    int t   = threadIdx.x;
    int r   = t >> 3;                          // output row 0..63
    int cb  = (t & 7) * 8;                     // output col base
    int lane = t & 31;
    int wid  = t >> 5;

    // staging geometry (2x 16B cp.async per thread per tile)
    int srow = t >> 4;                         // 0..31
    int scol = (t & 15) * 4;                   // 0..60
    int g0 = srow * HW + scol;                 // global float offset (rows 0..31)
    int g1 = g0 + 32 * HW;                     // rows 32..63
    int d0 = (srow + 1) * T + OCOL + scol;     // smem float offset (16B aligned)
    int d1 = d0 + 32 * T;
    uint32_t s00 = (uint32_t)__cvta_generic_to_shared(&buf[0][d0]);
    uint32_t s01 = (uint32_t)__cvta_generic_to_shared(&buf[0][d1]);
    uint32_t s10 = (uint32_t)__cvta_generic_to_shared(&buf[1][d0]);
    uint32_t s11 = (uint32_t)__cvta_generic_to_shared(&buf[1][d1]);

    // zero both buffers ONCE (halos stay zero; interior overwritten each step)
    for (int i = t; i < 2 * TILE; i += NT) ((float*)buf)[i] = 0.f;
    for (int i = t; i < CPB * CIN * 9; i += NT) {
        int cc = i / (CIN * 9);
        int rem = i - cc * (CIN * 9);
        ws[i] = w[(cog * CPB + cc) * (CIN * 9) + rem];
    }
    if (t < CIN) sc_s[t] = g_sc[b * CIN + t];
    __syncthreads();

    const float* xb = x + (size_t)b * CIN * NPIX;

    // prologue: async-stage raw tile 0
    CP16(s00, xb + g0);
    CP16(s01, xb + g1);
    CP_COMMIT();

    u64t a2[CPB][4];                           // acc as packed pairs
    float x2[CPB];
    #pragma unroll
    for (int cc = 0; cc < CPB; cc++) {
        x2[cc] = 0.f;
        #pragma unroll
        for (int p = 0; p < 4; p++) a2[cc][p] = 0ull;
    }

    for (int j = 0; j < CIN; j++) {
        // issue next tile's copy, then wait for the current tile
        if (j < CIN - 1) {
            const float* xn = xb + (size_t)(j + 1) * NPIX;
            if ((j + 1) & 1) { CP16(s10, xn + g0); CP16(s11, xn + g1); }
            else             { CP16(s00, xn + g0); CP16(s01, xn + g1); }
            CP_COMMIT();
            CP_WAIT1();
        } else {
            CP_WAIT0();
        }
        __syncthreads();                       // tile j ready; red free for reuse

        const float* A = buf[j & 1];

        // ---- conv: row-at-a-time, packed f32x2, 4 couts share u ----
        u64t v2[CPB][4];
        #pragma unroll
        for (int cc = 0; cc < CPB; cc++)
            #pragma unroll
            for (int p = 0; p < 4; p++) v2[cc][p] = 0ull;

        #pragma unroll 1
        for (int k = 0; k < 3; k++) {
            const float* p0 = A + (r + k) * T + 3 + cb;
            float us[10];
            #pragma unroll
            for (int s = 0; s < 10; s++) us[s] = p0[s];
            if (cb == 56) us[9] = 0.f;         // right halo (col 68 wraps)
            u64t up[9];
            #pragma unroll
            for (int s = 0; s < 9; s++) PACK2(up[s], us[s], us[s + 1]);

            #pragma unroll
            for (int cc = 0; cc < CPB; cc++) {
                const float* wp = &ws[cc * (CIN * 9) + j * 9 + k * 3];
                float wa = wp[0], wb = wp[1], wc = wp[2];
                u64t w0p, w1p, w2p;
                PACK2(w0p, wa, wa); PACK2(w1p, wb, wb); PACK2(w2p, wc, wc);
                #pragma unroll
                for (int p = 0; p < 4; p++) {
                    FMA2(v2[cc][p], up[2 * p],     w0p, v2[cc][p]);
                    FMA2(v2[cc][p], up[2 * p + 1], w1p, v2[cc][p]);
                    FMA2(v2[cc][p], up[2 * p + 2], w2p, v2[cc][p]);
                }
            }
        }

        // ---- partial sums (raw): sv2 = sum v^2, sav = sum acc*v ----
        float part[8];
        #pragma unroll
        for (int cc = 0; cc < CPB; cc++) {
            u64t s2 = 0ull, sa = 0ull;
            #pragma unroll
            for (int p = 0; p < 4; p++) {
                FMA2(s2, v2[cc][p], v2[cc][p], s2);
                FMA2(sa, a2[cc][p], v2[cc][p], sa);
            }
            float lo, hi;
            UNPACK2(lo, hi, s2); part[2 * cc] = lo + hi;
            UNPACK2(lo, hi, sa); part[2 * cc + 1] = lo + hi;
        }

        // stage-1: warp reduce 8 scalars, leaders write partials
        #pragma unroll
        for (int q = 0; q < 8; q++) {
            #pragma unroll
            for (int o = 16; o; o >>= 1)
                part[q] += __shfl_xor_sync(0xffffffffu, part[q], o);
        }
        if (lane == 0) {
            #pragma unroll
            for (int q = 0; q < 8; q++) red[q][wid] = part[q];
        }
        __syncthreads();

        // stage-2 (per-warp, no extra barrier) + mobius update
        float scj = sc_s[j];
        #pragma unroll
        for (int cc = 0; cc < CPB; cc++) {
            float sraw = (lane < 16) ? red[2 * cc][lane] : 0.f;
            float araw = (lane < 16) ? red[2 * cc + 1][lane] : 0.f;
            #pragma unroll
            for (int o = 16; o; o >>= 1) {
                sraw += __shfl_xor_sync(0xffffffffu, sraw, o);
                araw += __shfl_xor_sync(0xffffffffu, araw, o);
            }
            float sv2 = scj * scj * sraw;      // fold logmap scale
            float sav = scj * araw;

            float un  = fmaxf(sqrtf(sv2), MINN);
            float th  = tanhf(SQC * un);
            float m   = fminf(th, 0.996f);     // fold project(t)
            float gam = m / (SQC * un);
            float y2  = gam * gam * sv2;
            float xy  = gam * sav;
            float Aa  = 1.f + 2.f * C_CURV * xy + C_CURV * y2;
            float Bb  = 1.f - C_CURV * x2[cc];
            float den = fmaxf(1.f + 2.f * C_CURV * xy
                              + C_CURV * C_CURV * x2[cc] * y2, MINN);
            float rden = 1.f / den;
            float n2 = (Aa * Aa * x2[cc] + 2.f * Aa * Bb * xy + Bb * Bb * y2)
                       * rden * rden;
            float n  = fmaxf(sqrtf(n2), MINN);
            float ps = (n > MAXNORM) ? (MAXNORM / n) : 1.f;
            float ka = Aa * rden * ps;
            float kv = Bb * gam * rden * ps * scj;   // fold scale into kv

            u64t kap, kvp;
            PACK2(kap, ka, ka); PACK2(kvp, kv, kv);
            #pragma unroll
            for (int p = 0; p < 4; p++) {
                u64t tv;
                MUL2(tv, kvp, v2[cc][p]);
                FMA2(a2[cc][p], kap, a2[cc][p], tv);
            }
            float nn = fminf(n, MAXNORM);
            x2[cc] = nn * nn;
        }
    }

    // ---- bias step: y spatially constant -> only need sum(acc) ----
    {
        float part[8];
        #pragma unroll
        for (int cc = 0; cc < CPB; cc++) {
            float s = 0.f;
            #pragma unroll
            for (int p = 0; p < 4; p++) {
                float lo, hi; UNPACK2(lo, hi, a2[cc][p]); s += lo + hi;
            }
            part[cc] = s;
        }
        #pragma unroll
        for (int q = 0; q < CPB; q++) {
            #pragma unroll
            for (int o = 16; o; o >>= 1)
                part[q] += __shfl_xor_sync(0xffffffffu, part[q], o);
        }
        __syncthreads();                       // red free (all stage-2 reads done)
        if (lane == 0) {
            #pragma unroll
            for (int q = 0; q < CPB; q++) red[q][wid] = part[q];
        }
        __syncthreads();

        #pragma unroll
        for (int cc = 0; cc < CPB; cc++) {
            float sa = (lane < 16) ? red[cc][lane] : 0.f;
            #pragma unroll
            for (int o = 16; o; o >>= 1)
                sa += __shfl_xor_sync(0xffffffffu, sa, o);

            int co = cog * CPB + cc;
            float bh = g_bh[co];
            float y2 = (float)NPIX * bh * bh;
            float xy = bh * sa;
            float Aa  = 1.f + 2.f * C_CURV * xy + C_CURV * y2;
            float Bb  = 1.f - C_CURV * x2[cc];
            float den = fmaxf(1.f + 2.f * C_CURV * xy
                              + C_CURV * C_CURV * x2[cc] * y2, MINN);
            float rden = 1.f / den;
            float n2 = (Aa * Aa * x2[cc] + 2.f * Aa * Bb * xy + Bb * Bb * y2)
                       * rden * rden;
            float n  = fmaxf(sqrtf(n2), MINN);
            float ps = (n > MAXNORM) ? (MAXNORM / n) : 1.f;
            float ka = Aa * rden * ps;
            float kb = Bb * bh * rden * ps;

            float o8[8];
            #pragma unroll
            for (int p = 0; p < 4; p++) {
                float lo, hi; UNPACK2(lo, hi, a2[cc][p]);
                o8[2 * p]     = ka * lo + kb;
                o8[2 * p + 1] = ka * hi + kb;
            }
            float* op = out + (((size_t)b * COUT + co) * HW + r) * HW + cb;
            *reinterpret_cast<float4*>(op)     = make_float4(o8[0], o8[1], o8[2], o8[3]);
            *reinterpret_cast<float4*>(op + 4) = make_float4(o8[4], o8[5], o8[6], o8[7]);
        }
    }
}

// ---------------- launch ----------------
extern "C" void kernel_launch(void* const* d_in, const int* in_sizes, int n_in,
                              void* d_out, int out_size) {
    const float* x    = (const float*)d_in[0];
    const float* wgt  = (const float*)d_in[1];
    const float* bias = (const float*)d_in[2];
    float* out = (float*)d_out;

    scale_kernel<<<BS * CIN, 256>>>(x);
    bias_kernel<<<1, COUT>>>(bias);
    dim3 grid(COUT / CPB, BS);   // (32, 32)
    hypconv_kernel<<<grid, NT>>>(x, wgt, out);
}

// round 9
// speedup vs baseline: 1.6611x; 1.6611x over previous
#include <cuda_runtime.h>
#include <math.h>

// ---------------- constants ----------------
#define C_CURV 0.05f
#define SQC    0.22360679774997896f              // sqrt(0.05)
#define MAXNORM (0.996f / 0.22360679774997896f)  // (1-4e-3)/sqrt(c)
#define MINN   1e-15f

#define BS   32
#define CIN  64
#define COUT 128
#define HW   64
#define NPIX 4096      // 64*64
#define HPAD 66        // padded rows (0 and 65 are halo)
#define T    68        // smem tile row stride (floats)
#define OCOL 4         // input col ci -> smem col ci+4; left halo col 3 (always 0)

#define NT   512       // threads per block (main kernel)
#define CPB  4         // couts per block
#define TILE (HPAD * T)   // 4488 floats

// scratch (allocation-free rule: __device__ globals)
__device__ float g_sc[BS * CIN];   // logmap0 scale per (b,cin)
__device__ float g_bh[COUT];       // expmap0(bias)

// ---------------- kernel A: logmap0 scales ----------------
__global__ void scale_kernel(const float* __restrict__ x) {
    int bc = blockIdx.x;                       // 0..2047
    const float* xp = x + (size_t)bc * NPIX;
    float s = 0.f;
    for (int i = threadIdx.x; i < NPIX; i += 256) { float v = xp[i]; s += v * v; }
    __shared__ float red[8];
    #pragma unroll
    for (int o = 16; o; o >>= 1) s += __shfl_xor_sync(0xffffffffu, s, o);
    if ((threadIdx.x & 31) == 0) red[threadIdx.x >> 5] = s;
    __syncthreads();
    if (threadIdx.x == 0) {
        float tot = 0.f;
        #pragma unroll
        for (int w = 0; w < 8; w++) tot += red[w];
        float n = fmaxf(sqrtf(tot), MINN);
        float a = fminf(SQC * n, 1.f - 1e-7f);
        float art = 0.5f * (log1pf(a) - log1pf(-a));
        g_sc[bc] = art / (SQC * n);
    }
}

// ---------------- kernel B: hyperbolic bias ----------------
__global__ void bias_kernel(const float* __restrict__ bias) {
    __shared__ float red[4];
    int t = threadIdx.x;                       // 128 threads
    float v = bias[t];
    float s = v * v;
    #pragma unroll
    for (int o = 16; o; o >>= 1) s += __shfl_xor_sync(0xffffffffu, s, o);
    if ((t & 31) == 0) red[t >> 5] = s;
    __syncthreads();
    float tot = red[0] + red[1] + red[2] + red[3];
    float n = fmaxf(sqrtf(tot), MINN);
    g_bh[t] = tanhf(SQC * n) * v / (SQC * n);
}

// ---------------- main kernel ----------------
__global__ __launch_bounds__(NT, 1)
void hypconv_kernel(const float* __restrict__ x, const float* __restrict__ w,
                    float* __restrict__ out) {
    __shared__ float buf[2][TILE];             // double-buffered scaled padded tiles
    __shared__ float ws[CIN * 3 * CPB * 4];    // weights: [j][k][cc] float4 (w3=pad)
    __shared__ float sc_s[CIN];                // logmap scales for this batch
    __shared__ float red[8][16];
    __shared__ float kas[CPB], kvs[CPB];

    int b   = blockIdx.y;                      // 0..31
    int cog = blockIdx.x;                      // 0..31 (cout group)
    int t   = threadIdx.x;
    int r   = t >> 3;                          // output row 0..63
    int cb  = (t & 7) * 8;                     // output col base
    int lane = t & 31;
    int wid  = t >> 5;
    bool edge = (cb == 56);                    // rightmost column group

    // staging geometry (2 float4 per thread per tile)
    int srow = t >> 4;                         // 0..31
    int scol = (t & 15) * 4;                   // 0..60
    int g0 = srow * HW + scol;                 // global float offset (rows 0..31)
    int g1 = g0 + 32 * HW;                     // rows 32..63
    int d0 = (srow + 1) * T + OCOL + scol;     // smem float offset (16B aligned)
    int d1 = d0 + 32 * T;

    // zero both buffers ONCE (halos/cols 0..3 stay zero; interior overwritten)
    for (int i = t; i < 2 * TILE; i += NT) ((float*)buf)[i] = 0.f;
    // weights: ws[((j*3+k)*CPB+cc)*4+e]
    for (int i = t; i < CIN * 3 * CPB * 4; i += NT) {
        int e  = i & 3;
        int cc = (i >> 2) & 3;
        int k  = (i >> 4) % 3;
        int j  = i / 48;
        ws[i] = (e < 3) ? w[(cog * CPB + cc) * (CIN * 9) + j * 9 + k * 3 + e] : 0.f;
    }
    if (t < CIN) sc_s[t] = g_sc[b * CIN + t];
    __syncthreads();

    const float* xb = x + (size_t)b * CIN * NPIX;

    // stage tile 0 (scaled)
    {
        float s0 = sc_s[0];
        float4 a0 = *reinterpret_cast<const float4*>(xb + g0);
        float4 a1 = *reinterpret_cast<const float4*>(xb + g1);
        float* B = buf[0];
        *reinterpret_cast<float4*>(B + d0) =
            make_float4(a0.x * s0, a0.y * s0, a0.z * s0, a0.w * s0);
        *reinterpret_cast<float4*>(B + d1) =
            make_float4(a1.x * s0, a1.y * s0, a1.z * s0, a1.w * s0);
    }
    __syncthreads();

    float acc[CPB][8];
    #pragma unroll
    for (int cc = 0; cc < CPB; cc++)
        #pragma unroll
        for (int i = 0; i < 8; i++) acc[cc][i] = 0.f;
    float x2w = 0.f;                           // x2 for cout 'wid' (valid on wid<4)

    for (int j = 0; j < CIN; j++) {
        const float* A = buf[j & 1];

        // prefetch next channel's tile into registers (hidden under the conv)
        float4 pf0, pf1;
        if (j < CIN - 1) {
            const float* xn = xb + (size_t)(j + 1) * NPIX;
            pf0 = *reinterpret_cast<const float4*>(xn + g0);
            pf1 = *reinterpret_cast<const float4*>(xn + g1);
        }

        // ---- conv: row-at-a-time, 4 couts share the u row ----
        float v[CPB][8];
        #pragma unroll
        for (int cc = 0; cc < CPB; cc++)
            #pragma unroll
            for (int i = 0; i < 8; i++) v[cc][i] = 0.f;

        const float4* wsj = reinterpret_cast<const float4*>(ws + j * 48);
        #pragma unroll
        for (int k = 0; k < 3; k++) {
            const float* p0 = A + (r + k) * T + 3 + cb;
            float us[10];
            us[0] = p0[0];
            float4 ua = *reinterpret_cast<const float4*>(p0 + 1);
            float4 ub = *reinterpret_cast<const float4*>(p0 + 5);
            us[1] = ua.x; us[2] = ua.y; us[3] = ua.z; us[4] = ua.w;
            us[5] = ub.x; us[6] = ub.y; us[7] = ub.z; us[8] = ub.w;
            // right halo (padded col 65) = 0; predicate the load so the edge
            // thread never touches past-tile smem
            us[9] = edge ? 0.f : p0[9];

            #pragma unroll
            for (int cc = 0; cc < CPB; cc++) {
                float4 wk = wsj[k * CPB + cc];
                #pragma unroll
                for (int i = 0; i < 8; i++)
                    v[cc][i] += us[i] * wk.x + us[i + 1] * wk.y + us[i + 2] * wk.z;
            }
        }

        // ---- partial sums: sv2 = sum v^2, sav = sum acc*v ----
        float part[8];
        #pragma unroll
        for (int cc = 0; cc < CPB; cc++) {
            float sv2 = 0.f, sav = 0.f;
            #pragma unroll
            for (int i = 0; i < 8; i++) {
                sv2 += v[cc][i] * v[cc][i];
                sav += acc[cc][i] * v[cc][i];
            }
            part[2 * cc]     = sv2;
            part[2 * cc + 1] = sav;
        }

        // stage-1: warp reduce 8 scalars, leaders write partials
        #pragma unroll
        for (int q = 0; q < 8; q++) {
            #pragma unroll
            for (int o = 16; o; o >>= 1)
                part[q] += __shfl_xor_sync(0xffffffffu, part[q], o);
        }
        if (lane == 0) {
            #pragma unroll
            for (int q = 0; q < 8; q++) red[q][wid] = part[q];
        }

        // store prefetched (scaled) tile into the other buffer
        if (j < CIN - 1) {
            float s = sc_s[j + 1];
            float* B = buf[(j + 1) & 1];
            *reinterpret_cast<float4*>(B + d0) =
                make_float4(pf0.x * s, pf0.y * s, pf0.z * s, pf0.w * s);
            *reinterpret_cast<float4*>(B + d1) =
                make_float4(pf1.x * s, pf1.y * s, pf1.z * s, pf1.w * s);
        }
        __syncthreads();                       // red partials + next tile visible

        // ---- stage-2 + mobius: warp w (<4) owns cout w; halves do sv2/sav ----
        if (wid < 4) {
            int l16 = lane & 15;
            float val = red[2 * wid + (lane >> 4)][l16];
            #pragma unroll
            for (int o = 8; o; o >>= 1)
                val += __shfl_xor_sync(0xffffffffu, val, o);
            float sv2 = __shfl_sync(0xffffffffu, val, 0);
            float sav = __shfl_sync(0xffffffffu, val, 16);

            float un  = fmaxf(sqrtf(sv2), MINN);
            float th  = tanhf(SQC * un);
            float m   = fminf(th, 0.996f);     // fold project(t)
            float gam = m / (SQC * un);
            float y2  = gam * gam * sv2;
            float xy  = gam * sav;
            float Aa  = 1.f + 2.f * C_CURV * xy + C_CURV * y2;
            float Bb  = 1.f - C_CURV * x2w;
            float den = fmaxf(1.f + 2.f * C_CURV * xy
                              + C_CURV * C_CURV * x2w * y2, MINN);
            float rden = 1.f / den;
            float n2 = (Aa * Aa * x2w + 2.f * Aa * Bb * xy + Bb * Bb * y2)
                       * rden * rden;
            float n  = fmaxf(sqrtf(n2), MINN);
            float ps = (n > MAXNORM) ? (MAXNORM / n) : 1.f;
            if (lane == 0) {
                kas[wid] = Aa * rden * ps;
                kvs[wid] = Bb * gam * rden * ps;
            }
            float nn = fminf(n, MAXNORM);
            x2w = nn * nn;
        }
        __syncthreads();                       // kas/kvs ready

        // ---- acc update (all threads) ----
        #pragma unroll
        for (int cc = 0; cc < CPB; cc++) {
            float ka = kas[cc], kv = kvs[cc];
            #pragma unroll
            for (int i = 0; i < 8; i++)
                acc[cc][i] = ka * acc[cc][i] + kv * v[cc][i];
        }
    }

    // ---- bias step: y spatially constant -> only need sum(acc) ----
    {
        float part[CPB];
        #pragma unroll
        for (int cc = 0; cc < CPB; cc++) {
            float s = 0.f;
            #pragma unroll
            for (int i = 0; i < 8; i++) s += acc[cc][i];
            part[cc] = s;
        }
        #pragma unroll
        for (int q = 0; q < CPB; q++) {
            #pragma unroll
            for (int o = 16; o; o >>= 1)
                part[q] += __shfl_xor_sync(0xffffffffu, part[q], o);
        }
        if (lane == 0) {
            #pragma unroll
            for (int q = 0; q < CPB; q++) red[q][wid] = part[q];
        }
        __syncthreads();

        if (wid < 4) {
            float val = (lane < 16) ? red[wid][lane] : 0.f;
            #pragma unroll
            for (int o = 8; o; o >>= 1)
                val += __shfl_xor_sync(0xffffffffu, val, o);
            float sa = __shfl_sync(0xffffffffu, val, 0);

            float bh = g_bh[cog * CPB + wid];
            float y2 = (float)NPIX * bh * bh;
            float xy = bh * sa;
            float Aa  = 1.f + 2.f * C_CURV * xy + C_CURV * y2;
            float Bb  = 1.f - C_CURV * x2w;
            float den = fmaxf(1.f + 2.f * C_CURV * xy
                              + C_CURV * C_CURV * x2w * y2, MINN);
            float rden = 1.f / den;
            float n2 = (Aa * Aa * x2w + 2.f * Aa * Bb * xy + Bb * Bb * y2)
                       * rden * rden;
            float n  = fmaxf(sqrtf(n2), MINN);
            float ps = (n > MAXNORM) ? (MAXNORM / n) : 1.f;
            if (lane == 0) {
                kas[wid] = Aa * rden * ps;          // ka
                kvs[wid] = Bb * bh * rden * ps;     // kb (additive)
            }
        }
        __syncthreads();

        #pragma unroll
        for (int cc = 0; cc < CPB; cc++) {
            float ka = kas[cc], kb = kvs[cc];
            int co = cog * CPB + cc;
            float o8[8];
            #pragma unroll
            for (int i = 0; i < 8; i++) o8[i] = ka * acc[cc][i] + kb;
            float* op = out + (((size_t)b * COUT + co) * HW + r) * HW + cb;
            *reinterpret_cast<float4*>(op)     = make_float4(o8[0], o8[1], o8[2], o8[3]);
            *reinterpret_cast<float4*>(op + 4) = make_float4(o8[4], o8[5], o8[6], o8[7]);
        }
    }
}

// ---------------- launch ----------------
extern "C" void kernel_launch(void* const* d_in, const int* in_sizes, int n_in,
                              void* d_out, int out_size) {
    const float* x    = (const float*)d_in[0];
    const float* wgt  = (const float*)d_in[1];
    const float* bias = (const float*)d_in[2];
    float* out = (float*)d_out;

    scale_kernel<<<BS * CIN, 256>>>(x);
    bias_kernel<<<1, COUT>>>(bias);
    dim3 grid(COUT / CPB, BS);   // (32, 32)
    hypconv_kernel<<<grid, NT>>>(x, wgt, out);
}

// round 11
// speedup vs baseline: 1.9795x; 1.1917x over previous
#include <cuda_runtime.h>
#include <math.h>

// ---------------- constants ----------------
#define C_CURV 0.05f
#define SQC    0.22360679774997896f              // sqrt(0.05)
#define MAXNORM (0.996f / 0.22360679774997896f)  // (1-4e-3)/sqrt(c)
#define MN2F   19.84032f                         // MAXNORM^2
#define MINN   1e-15f

#define BS   32
#define CIN  64
#define COUT 128
#define HW   64
#define NPIX 4096      // 64*64
#define HPAD 66        // padded rows (0 and 65 are halo)
#define T    68        // smem tile row stride (floats)
#define OCOL 4         // input col ci -> smem col ci+4; left halo col 3 (always 0)

#define NT   512       // threads per block (main kernel)
#define CPB  4         // couts per block
#define TILE (HPAD * T)   // 4488 floats

// scratch (allocation-free rule: __device__ globals)
__device__ float g_sc[BS * CIN];   // logmap0 scale per (b,cin)
__device__ float g_bh[COUT];       // expmap0(bias)

// ---------------- kernel A: logmap0 scales ----------------
__global__ void scale_kernel(const float* __restrict__ x) {
    int bc = blockIdx.x;                       // 0..2047
    const float4* xp = reinterpret_cast<const float4*>(x + (size_t)bc * NPIX);
    float s = 0.f;
    for (int i = threadIdx.x; i < NPIX / 4; i += 256) {
        float4 a = xp[i];
        s += a.x * a.x + a.y * a.y + a.z * a.z + a.w * a.w;
    }
    __shared__ float red[8];
    #pragma unroll
    for (int o = 16; o; o >>= 1) s += __shfl_xor_sync(0xffffffffu, s, o);
    if ((threadIdx.x & 31) == 0) red[threadIdx.x >> 5] = s;
    __syncthreads();
    if (threadIdx.x == 0) {
        float tot = 0.f;
        #pragma unroll
        for (int w = 0; w < 8; w++) tot += red[w];
        float n = fmaxf(sqrtf(tot), MINN);
        float a = fminf(SQC * n, 1.f - 1e-7f);
        float art = 0.5f * (log1pf(a) - log1pf(-a));
        g_sc[bc] = art / (SQC * n);
    }
}

// ---------------- kernel B: hyperbolic bias ----------------
__global__ void bias_kernel(const float* __restrict__ bias) {
    __shared__ float red[4];
    int t = threadIdx.x;                       // 128 threads
    float v = bias[t];
    float s = v * v;
    #pragma unroll
    for (int o = 16; o; o >>= 1) s += __shfl_xor_sync(0xffffffffu, s, o);
    if ((t & 31) == 0) red[t >> 5] = s;
    __syncthreads();
    float tot = red[0] + red[1] + red[2] + red[3];
    float n = fmaxf(sqrtf(tot), MINN);
    g_bh[t] = tanhf(SQC * n) * v / (SQC * n);
}

// ---------------- main kernel ----------------
__global__ __launch_bounds__(NT, 1)
void hypconv_kernel(const float* __restrict__ x, const float* __restrict__ w,
                    float* __restrict__ out) {
    __shared__ float buf[2][TILE];             // double-buffered scaled padded tiles
    __shared__ float ws[CIN * 3 * CPB * 4];    // weights: [j][k][cc] float4 (w3=pad)
    __shared__ float sc_s[CIN];                // logmap scales for this batch
    __shared__ float red[8][16];
    __shared__ float kas[CPB], kvs[CPB];

    int b   = blockIdx.y;                      // 0..31
    int cog = blockIdx.x;                      // 0..31 (cout group)
    int t   = threadIdx.x;
    int r   = t >> 3;                          // output row 0..63
    int cb  = (t & 7) * 8;                     // output col base
    int lane = t & 31;
    int wid  = t >> 5;
    bool edge = (cb == 56);                    // rightmost column group

    // staging geometry (2 float4 per thread per tile)
    int srow = t >> 4;                         // 0..31
    int scol = (t & 15) * 4;                   // 0..60
    int g0 = srow * HW + scol;                 // global float offset (rows 0..31)
    int g1 = g0 + 32 * HW;                     // rows 32..63
    int d0 = (srow + 1) * T + OCOL + scol;     // smem float offset (16B aligned)
    int d1 = d0 + 32 * T;

    // zero both buffers ONCE (halos/cols 0..3 stay zero; interior overwritten)
    for (int i = t; i < 2 * TILE; i += NT) ((float*)buf)[i] = 0.f;
    // weights: ws[((j*3+k)*CPB+cc)*4+e]
    for (int i = t; i < CIN * 3 * CPB * 4; i += NT) {
        int e  = i & 3;
        int cc = (i >> 2) & 3;
        int k  = (i >> 4) % 3;
        int j  = i / 48;
        ws[i] = (e < 3) ? w[(cog * CPB + cc) * (CIN * 9) + j * 9 + k * 3 + e] : 0.f;
    }
    if (t < CIN) sc_s[t] = g_sc[b * CIN + t];
    __syncthreads();

    const float* xb = x + (size_t)b * CIN * NPIX;

    // stage tile 0 (scaled)
    {
        float s0 = sc_s[0];
        float4 a0 = *reinterpret_cast<const float4*>(xb + g0);
        float4 a1 = *reinterpret_cast<const float4*>(xb + g1);
        float* B = buf[0];
        *reinterpret_cast<float4*>(B + d0) =
            make_float4(a0.x * s0, a0.y * s0, a0.z * s0, a0.w * s0);
        *reinterpret_cast<float4*>(B + d1) =
            make_float4(a1.x * s0, a1.y * s0, a1.z * s0, a1.w * s0);
    }
    __syncthreads();

    float acc[CPB][8];
    #pragma unroll
    for (int cc = 0; cc < CPB; cc++)
        #pragma unroll
        for (int i = 0; i < 8; i++) acc[cc][i] = 0.f;
    float x2w = 0.f;                           // x2 for cout 'wid' (valid on wid<4)

    for (int j = 0; j < CIN; j++) {
        const float* A = buf[j & 1];

        // prefetch next channel's tile into registers (hidden under the conv)
        float4 pf0, pf1;
        if (j < CIN - 1) {
            const float* xn = xb + (size_t)(j + 1) * NPIX;
            pf0 = *reinterpret_cast<const float4*>(xn + g0);
            pf1 = *reinterpret_cast<const float4*>(xn + g1);
        }

        // ---- conv: row-at-a-time, 4 couts share the u row ----
        float v[CPB][8];
        #pragma unroll
        for (int cc = 0; cc < CPB; cc++)
            #pragma unroll
            for (int i = 0; i < 8; i++) v[cc][i] = 0.f;

        const float4* wsj = reinterpret_cast<const float4*>(ws + j * 48);
        #pragma unroll
        for (int k = 0; k < 3; k++) {
            const float* p0 = A + (r + k) * T + 3 + cb;
            float us[10];
            us[0] = p0[0];
            float4 ua = *reinterpret_cast<const float4*>(p0 + 1);
            float4 ub = *reinterpret_cast<const float4*>(p0 + 5);
            us[1] = ua.x; us[2] = ua.y; us[3] = ua.z; us[4] = ua.w;
            us[5] = ub.x; us[6] = ub.y; us[7] = ub.z; us[8] = ub.w;
            us[9] = edge ? 0.f : p0[9];        // right halo (padded col 65) = 0

            #pragma unroll
            for (int cc = 0; cc < CPB; cc++) {
                float4 wk = wsj[k * CPB + cc];
                #pragma unroll
                for (int i = 0; i < 8; i++)
                    v[cc][i] += us[i] * wk.x + us[i + 1] * wk.y + us[i + 2] * wk.z;
            }
        }

        // ---- partial sums: sv2 = sum v^2, sav = sum acc*v ----
        float part[8];
        #pragma unroll
        for (int cc = 0; cc < CPB; cc++) {
            float sv2 = 0.f, sav = 0.f;
            #pragma unroll
            for (int i = 0; i < 8; i++) {
                sv2 += v[cc][i] * v[cc][i];
                sav += acc[cc][i] * v[cc][i];
            }
            part[2 * cc]     = sv2;
            part[2 * cc + 1] = sav;
        }

        // stage-1: role-splitting butterfly — 8 scalars in 9 shfl
        {
            bool h16 = (lane & 16);
            float tt[4];
            #pragma unroll
            for (int q = 0; q < 4; q++) {
                float keep = h16 ? part[q + 4] : part[q];
                float send = h16 ? part[q]     : part[q + 4];
                tt[q] = keep + __shfl_xor_sync(0xffffffffu, send, 16);
            }
            bool h8 = (lane & 8);
            float ss[2];
            #pragma unroll
            for (int q = 0; q < 2; q++) {
                float keep = h8 ? tt[q + 2] : tt[q];
                float send = h8 ? tt[q]     : tt[q + 2];
                ss[q] = keep + __shfl_xor_sync(0xffffffffu, send, 8);
            }
            bool h4 = (lane & 4);
            float keep = h4 ? ss[1] : ss[0];
            float send = h4 ? ss[0] : ss[1];
            float u = keep + __shfl_xor_sync(0xffffffffu, send, 4);
            u += __shfl_xor_sync(0xffffffffu, u, 2);
            u += __shfl_xor_sync(0xffffffffu, u, 1);
            if ((lane & 3) == 0) red[lane >> 2][wid] = u;
        }

        // store prefetched (scaled) tile into the other buffer
        if (j < CIN - 1) {
            float s = sc_s[j + 1];
            float* B = buf[(j + 1) & 1];
            *reinterpret_cast<float4*>(B + d0) =
                make_float4(pf0.x * s, pf0.y * s, pf0.z * s, pf0.w * s);
            *reinterpret_cast<float4*>(B + d1) =
                make_float4(pf1.x * s, pf1.y * s, pf1.z * s, pf1.w * s);
        }
        __syncthreads();                       // red partials + next tile visible

        // ---- stage-2 + mobius: warp w (<4) owns cout w; halves do sv2/sav ----
        if (wid < 4) {
            int l16 = lane & 15;
            float val = red[2 * wid + (lane >> 4)][l16];
            #pragma unroll
            for (int o = 8; o; o >>= 1)
                val += __shfl_xor_sync(0xffffffffu, val, o);
            float sv2 = __shfl_sync(0xffffffffu, val, 0);
            float sav = __shfl_sync(0xffffffffu, val, 16);

            // fast path: tanh(z)/z poly in z^2 (z^2 = C*sv2), no sqrt/tanh/div
            float z2 = C_CURV * sv2;
            float gam = 1.f + z2 * (-0.33333334f
                      + z2 * (0.13333334f - z2 * 0.05396825f));
            if (z2 > 0.04f) {                  // exact fallback (incl. clamp)
                float un = fmaxf(sqrtf(sv2), MINN);
                float sz = SQC * un;
                gam = fminf(tanhf(sz), 0.996f) / sz;
            }
            float y2 = gam * gam * sv2;
            float xy = gam * sav;
            float Aa  = 1.f + 2.f * C_CURV * xy + C_CURV * y2;
            float Bb  = 1.f - C_CURV * x2w;
            float den = fmaxf(1.f + 2.f * C_CURV * xy
                              + C_CURV * C_CURV * x2w * y2, MINN);
            float rden = __fdividef(1.f, den);
            float n2 = (Aa * Aa * x2w + 2.f * Aa * Bb * xy + Bb * Bb * y2)
                       * rden * rden;
            float ps = 1.f;
            if (n2 > MN2F) ps = MAXNORM / fmaxf(sqrtf(n2), MINN);
            if (lane == 0) {
                kas[wid] = Aa * rden * ps;
                kvs[wid] = Bb * gam * rden * ps;
            }
            x2w = fminf(n2, MN2F);             // == min(n, MAXNORM)^2
        }
        __syncthreads();                       // kas/kvs ready

        // ---- acc update (all threads) ----
        #pragma unroll
        for (int cc = 0; cc < CPB; cc++) {
            float ka = kas[cc], kv = kvs[cc];
            #pragma unroll
            for (int i = 0; i < 8; i++)
                acc[cc][i] = ka * acc[cc][i] + kv * v[cc][i];
        }
    }

    // ---- bias step: y spatially constant -> only need sum(acc) ----
    {
        float part[8];
        #pragma unroll
        for (int cc = 0; cc < CPB; cc++) {
            float s = 0.f;
            #pragma unroll
            for (int i = 0; i < 8; i++) s += acc[cc][i];
            part[cc] = s;
        }
        #pragma unroll
        for (int cc = CPB; cc < 8; cc++) part[cc] = 0.f;

        // same role-splitting reduce (scalars 4..7 are zero, harmless)
        {
            bool h16 = (lane & 16);
            float tt[4];
            #pragma unroll
            for (int q = 0; q < 4; q++) {
                float keep = h16 ? part[q + 4] : part[q];
                float send = h16 ? part[q]     : part[q + 4];
                tt[q] = keep + __shfl_xor_sync(0xffffffffu, send, 16);
            }
            bool h8 = (lane & 8);
            float ss[2];
            #pragma unroll
            for (int q = 0; q < 2; q++) {
                float keep = h8 ? tt[q + 2] : tt[q];
                float send = h8 ? tt[q]     : tt[q + 2];
                ss[q] = keep + __shfl_xor_sync(0xffffffffu, send, 8);
            }
            bool h4 = (lane & 4);
            float keep = h4 ? ss[1] : ss[0];
            float send = h4 ? ss[0] : ss[1];
            float u = keep + __shfl_xor_sync(0xffffffffu, send, 4);
            u += __shfl_xor_sync(0xffffffffu, u, 2);
            u += __shfl_xor_sync(0xffffffffu, u, 1);
            if ((lane & 3) == 0) red[lane >> 2][wid] = u;
        }
        __syncthreads();

        if (wid < 4) {
            float val = (lane < 16) ? red[wid][lane] : 0.f;
            #pragma unroll
            for (int o = 8; o; o >>= 1)
                val += __shfl_xor_sync(0xffffffffu, val, o);
            float sa = __shfl_sync(0xffffffffu, val, 0);

            float bh = g_bh[cog * CPB + wid];
            float y2 = (float)NPIX * bh * bh;
            float xy = bh * sa;
            float Aa  = 1.f + 2.f * C_CURV * xy + C_CURV * y2;
            float Bb  = 1.f - C_CURV * x2w;
            float den = fmaxf(1.f + 2.f * C_CURV * xy
                              + C_CURV * C_CURV * x2w * y2, MINN);
            float rden = 1.f / den;
            float n2 = (Aa * Aa * x2w + 2.f * Aa * Bb * xy + Bb * Bb * y2)
                       * rden * rden;
            float n  = fmaxf(sqrtf(n2), MINN);
            float ps = (n > MAXNORM) ? (MAXNORM / n) : 1.f;
            if (lane == 0) {
                kas[wid] = Aa * rden * ps;          // ka
                kvs[wid] = Bb * bh * rden * ps;     // kb (additive)
            }
        }
        __syncthreads();

        #pragma unroll
        for (int cc = 0; cc < CPB; cc++) {
            float ka = kas[cc], kb = kvs[cc];
            int co = cog * CPB + cc;
            float o8[8];
            #pragma unroll
            for (int i = 0; i < 8; i++) o8[i] = ka * acc[cc][i] + kb;
            float* op = out + (((size_t)b * COUT + co) * HW + r) * HW + cb;
            *reinterpret_cast<float4*>(op)     = make_float4(o8[0], o8[1], o8[2], o8[3]);
            *reinterpret_cast<float4*>(op + 4) = make_float4(o8[4], o8[5], o8[6], o8[7]);
        }
    }
}

// ---------------- launch ----------------
extern "C" void kernel_launch(void* const* d_in, const int* in_sizes, int n_in,
                              void* d_out, int out_size) {
    const float* x    = (const float*)d_in[0];
    const float* wgt  = (const float*)d_in[1];
    const float* bias = (const float*)d_in[2];
    float* out = (float*)d_out;

    scale_kernel<<<BS * CIN, 256>>>(x);
    bias_kernel<<<1, COUT>>>(bias);
    dim3 grid(COUT / CPB, BS);   // (32, 32)
    hypconv_kernel<<<grid, NT>>>(x, wgt, out);
}